// round 5
// baseline (speedup 1.0000x reference)
#include <cuda_runtime.h>
#include <math.h>
#include <stdint.h>

#define ROWS 128
#define NT   256
#define KQ   512
#define KC   768
#define HID  128
#define DIMO 512
#define SCALE 0.17677669529663687f
#define SQRTD 22.627416997969522f

#define SQ 132
#define SA 36
#define SB 136

#define OFF_Q  0
#define OFF_A  16896
#define OFF_B  21504
#define OFF_S  25856
#define OFF_SS 26368
#define SMEMF  26496

__device__ __forceinline__ float tf(float x) {
    uint32_t r; asm("cvt.rna.tf32.f32 %0, %1;" : "=r"(r) : "f"(x));
    return __uint_as_float(r);
}

__device__ __forceinline__ void mma8(float* c, uint32_t a0, uint32_t a1, uint32_t a2,
                                     uint32_t a3, uint32_t b0, uint32_t b1) {
    asm volatile(
        "mma.sync.aligned.m16n8k8.row.col.f32.tf32.tf32.f32 "
        "{%0,%1,%2,%3},{%4,%5,%6,%7},{%8,%9},{%0,%1,%2,%3};"
        : "+f"(c[0]), "+f"(c[1]), "+f"(c[2]), "+f"(c[3])
        : "r"(a0), "r"(a1), "r"(a2), "r"(a3), "r"(b0), "r"(b1));
}

// Projection GEMM: [128 rows x 128 cols] += src[128 x K] @ W[K x 128], tf32.
// Warp wr=warp/2 owns rows 32*wr.., wc=warp&1 owns cols 64*wc.. ; acc[mt*8+nt][4].
template <int KTOT>
__device__ __forceinline__ void gemm(float (*acc)[4], const float* __restrict__ src, int ld,
                                     const float* __restrict__ W, float* sA, float* sB,
                                     int rowBase, int tid, int wr, int wc, int g, int t) {
#pragma unroll
    for (int i = 0; i < 16; i++) { acc[i][0] = 0.f; acc[i][1] = 0.f; acc[i][2] = 0.f; acc[i][3] = 0.f; }
#pragma unroll 1
    for (int kc = 0; kc < KTOT; kc += 32) {
#pragma unroll
        for (int i = 0; i < 8; i++) {   // A chunk: 128 rows x 32 k
            int idx = tid + i * NT;
            int r = idx >> 4, c2 = (idx & 15) << 1;
            float2 v = *(const float2*)(src + (size_t)(rowBase + r) * ld + kc + c2);
            sA[r * SA + c2] = tf(v.x);
            sA[r * SA + c2 + 1] = tf(v.y);
        }
#pragma unroll
        for (int i = 0; i < 4; i++) {   // B chunk: 32 k x 128 n
            int idx = tid + i * NT;
            int r = idx >> 5, c4 = (idx & 31) << 2;
            float4 v = *(const float4*)(W + (size_t)(kc + r) * HID + c4);
            float* d = sB + r * SB + c4;
            d[0] = tf(v.x); d[1] = tf(v.y); d[2] = tf(v.z); d[3] = tf(v.w);
        }
        __syncthreads();
#pragma unroll
        for (int s8 = 0; s8 < 4; s8++) {
            int k0 = s8 * 8 + t;
            uint32_t a[2][4];
#pragma unroll
            for (int mt = 0; mt < 2; mt++) {
                int r0 = wr * 32 + mt * 16 + g;
                a[mt][0] = __float_as_uint(sA[r0 * SA + k0]);
                a[mt][1] = __float_as_uint(sA[(r0 + 8) * SA + k0]);
                a[mt][2] = __float_as_uint(sA[r0 * SA + k0 + 4]);
                a[mt][3] = __float_as_uint(sA[(r0 + 8) * SA + k0 + 4]);
            }
#pragma unroll
            for (int nt = 0; nt < 8; nt++) {
                int col = wc * 64 + nt * 8 + g;
                uint32_t b0 = __float_as_uint(sB[k0 * SB + col]);
                uint32_t b1 = __float_as_uint(sB[(k0 + 4) * SB + col]);
                mma8(acc[nt],     a[0][0], a[0][1], a[0][2], a[0][3], b0, b1);
                mma8(acc[8 + nt], a[1][0], a[1][1], a[1][2], a[1][3], b0, b1);
            }
        }
        __syncthreads();
    }
}

__global__ void __launch_bounds__(NT, 1) lca_kernel(
    const float* __restrict__ x, const float* __restrict__ ctx,
    const float* __restrict__ Wq, const float* __restrict__ Wk,
    const float* __restrict__ Wv, const float* __restrict__ Wo,
    const float* __restrict__ bo, const float* __restrict__ gg,
    float* __restrict__ out) {
    extern __shared__ float sm[];
    float* sQ  = sm + OFF_Q;   // 128 x 132 (q -> out tile, tf32 bits for phase D)
    float* sA  = sm + OFF_A;
    float* sB  = sm + OFF_B;
    float* sS  = sm + OFF_S;   // s[row][head]
    float* sSS = sm + OFF_SS;  // row sum-of-squares

    int tid = threadIdx.x;
    int warp = tid >> 5, lane = tid & 31;
    int wr = warp >> 1, wc = warp & 1, g = lane >> 2, t = lane & 3;
    int rowBase = blockIdx.x * ROWS;
    if (tid < ROWS) sSS[tid] = 0.f;

    float acc[16][4];

    // ---- Phase 1: q = x @ Wq -> sQ ----
    gemm<KQ>(acc, x, KQ, Wq, sA, sB, rowBase, tid, wr, wc, g, t);
#pragma unroll
    for (int mt = 0; mt < 2; mt++)
#pragma unroll
        for (int nt = 0; nt < 8; nt++) {
            int r = wr * 32 + mt * 16 + g, c = wc * 64 + nt * 8 + 2 * t;
            sQ[r * SQ + c]           = acc[mt * 8 + nt][0];
            sQ[r * SQ + c + 1]       = acc[mt * 8 + nt][1];
            sQ[(r + 8) * SQ + c]     = acc[mt * 8 + nt][2];
            sQ[(r + 8) * SQ + c + 1] = acc[mt * 8 + nt][3];
        }
    __syncthreads();

    // softmax per (row, head), * scale, in place
    for (int task = tid; task < ROWS * 4; task += NT) {
        int r = task >> 2, h = task & 3;
        float* p = sQ + r * SQ + h * 32;
        float m = -1e30f;
        for (int j = 0; j < 32; j++) m = fmaxf(m, p[j]);
        float s = 0.f;
        for (int j = 0; j < 32; j++) s += __expf(p[j] - m);
        float inv = SCALE / s;
        for (int j = 0; j < 32; j++) p[j] = __expf(p[j] - m) * inv;
    }
    __syncthreads();

    // ---- Phase 2: k = sigmoid(ctx @ Wk); s[row][head] = sum_d k*q ----
    gemm<KC>(acc, ctx, KC, Wk, sA, sB, rowBase, tid, wr, wc, g, t);
    {
        float part[2][2][2] = {};  // [mt][row-half][head-in-wc]
#pragma unroll
        for (int mt = 0; mt < 2; mt++)
#pragma unroll
            for (int nt = 0; nt < 8; nt++) {
                int hl = nt >> 2;
                int r = wr * 32 + mt * 16 + g, c = wc * 64 + nt * 8 + 2 * t;
#pragma unroll
                for (int i = 0; i < 4; i++) {
                    int rr = r + (i >> 1) * 8, cc = c + (i & 1);
                    float kv = 1.f / (1.f + __expf(-acc[mt * 8 + nt][i]));
                    part[mt][i >> 1][hl] += kv * sQ[rr * SQ + cc];
                }
            }
#pragma unroll
        for (int mt = 0; mt < 2; mt++)
#pragma unroll
            for (int rh = 0; rh < 2; rh++)
#pragma unroll
                for (int hl = 0; hl < 2; hl++) {
                    float v = part[mt][rh][hl];
                    v += __shfl_xor_sync(0xffffffffu, v, 1);
                    v += __shfl_xor_sync(0xffffffffu, v, 2);
                    if (t == 0)
                        sS[(wr * 32 + mt * 16 + rh * 8 + g) * 4 + wc * 2 + hl] = v;
                }
    }

    // ---- Phase 3: v = ctx @ Wv; out = s*v -> sQ (tf32-converted) ----
    gemm<KC>(acc, ctx, KC, Wv, sA, sB, rowBase, tid, wr, wc, g, t);
#pragma unroll
    for (int mt = 0; mt < 2; mt++)
#pragma unroll
        for (int nt = 0; nt < 8; nt++) {
            int hl = nt >> 2;
            int r = wr * 32 + mt * 16 + g, c = wc * 64 + nt * 8 + 2 * t;
#pragma unroll
            for (int i = 0; i < 4; i++) {
                int rr = r + (i >> 1) * 8, cc = c + (i & 1);
                float s = sS[rr * 4 + wc * 2 + hl];
                sQ[rr * SQ + cc] = tf(s * acc[mt * 8 + nt][i]);
            }
        }
    __syncthreads();

    // ---- Phase 4: y = out @ Wo + bo; accumulate row sum-squares ----
#pragma unroll 1
    for (int nc = 0; nc < 4; nc++) {
#pragma unroll
        for (int i = 0; i < 16; i++) { acc[i][0] = 0.f; acc[i][1] = 0.f; acc[i][2] = 0.f; acc[i][3] = 0.f; }
#pragma unroll 1
        for (int kc = 0; kc < 128; kc += 32) {
#pragma unroll
            for (int i = 0; i < 4; i++) {
                int idx = tid + i * NT;
                int r = idx >> 5, c4 = (idx & 31) << 2;
                float4 v = *(const float4*)(Wo + (size_t)(kc + r) * DIMO + nc * 128 + c4);
                float* d = sB + r * SB + c4;
                d[0] = tf(v.x); d[1] = tf(v.y); d[2] = tf(v.z); d[3] = tf(v.w);
            }
            __syncthreads();
#pragma unroll
            for (int s8 = 0; s8 < 4; s8++) {
                int k0 = kc + s8 * 8 + t;
                int kk = s8 * 8 + t;
                uint32_t a[2][4];
#pragma unroll
                for (int mt = 0; mt < 2; mt++) {
                    int r0 = wr * 32 + mt * 16 + g;
                    a[mt][0] = __float_as_uint(sQ[r0 * SQ + k0]);
                    a[mt][1] = __float_as_uint(sQ[(r0 + 8) * SQ + k0]);
                    a[mt][2] = __float_as_uint(sQ[r0 * SQ + k0 + 4]);
                    a[mt][3] = __float_as_uint(sQ[(r0 + 8) * SQ + k0 + 4]);
                }
#pragma unroll
                for (int nt = 0; nt < 8; nt++) {
                    int col = wc * 64 + nt * 8 + g;
                    uint32_t b0 = __float_as_uint(sB[kk * SB + col]);
                    uint32_t b1 = __float_as_uint(sB[(kk + 4) * SB + col]);
                    mma8(acc[nt],     a[0][0], a[0][1], a[0][2], a[0][3], b0, b1);
                    mma8(acc[8 + nt], a[1][0], a[1][1], a[1][2], a[1][3], b0, b1);
                }
            }
            __syncthreads();
        }
        float rss[2][2] = {};
#pragma unroll
        for (int mt = 0; mt < 2; mt++)
#pragma unroll
            for (int nt = 0; nt < 8; nt++) {
                int r = wr * 32 + mt * 16 + g, c = nc * 128 + wc * 64 + nt * 8 + 2 * t;
#pragma unroll
                for (int i = 0; i < 4; i++) {
                    int rr = r + (i >> 1) * 8, cc = c + (i & 1);
                    float y = acc[mt * 8 + nt][i] + __ldg(bo + cc);
                    out[(size_t)(rowBase + rr) * DIMO + cc] = y;
                    rss[mt][i >> 1] += y * y;
                }
            }
#pragma unroll
        for (int mt = 0; mt < 2; mt++)
#pragma unroll
            for (int rh = 0; rh < 2; rh++) {
                float v = rss[mt][rh];
                v += __shfl_xor_sync(0xffffffffu, v, 1);
                v += __shfl_xor_sync(0xffffffffu, v, 2);
                if (t == 0) atomicAdd(&sSS[wr * 32 + mt * 16 + rh * 8 + g], v);
            }
    }
    __syncthreads();

    // ---- Phase 5: RMS-normalize in place (y is L2-hot) ----
    for (int i4 = tid; i4 < ROWS * DIMO / 4; i4 += NT) {
        int r = i4 >> 7, c4 = (i4 & 127) << 2;
        float* p = out + (size_t)(rowBase + r) * DIMO + c4;
        float4 y = *(float4*)p;
        float sc = rsqrtf(fmaxf(sSS[r], 1e-24f)) * SQRTD;
        float4 gv = *(const float4*)(gg + c4);
        y.x *= sc * gv.x; y.y *= sc * gv.y; y.z *= sc * gv.z; y.w *= sc * gv.w;
        *(float4*)p = y;
    }
}

extern "C" void kernel_launch(void* const* d_in, const int* in_sizes, int n_in,
                              void* d_out, int out_size) {
    const float* x   = (const float*)d_in[0];
    const float* ctx = (const float*)d_in[1];
    const float* Wq  = (const float*)d_in[2];
    const float* Wk  = (const float*)d_in[3];
    const float* Wv  = (const float*)d_in[4];
    const float* Wo  = (const float*)d_in[5];
    const float* bo  = (const float*)d_in[6];
    const float* gg  = (const float*)d_in[7];
    cudaFuncSetAttribute(lca_kernel, cudaFuncAttributeMaxDynamicSharedMemorySize, SMEMF * 4);
    lca_kernel<<<512, NT, SMEMF * 4>>>(x, ctx, Wq, Wk, Wv, Wo, bo, gg, (float*)d_out);
}

// round 6
// speedup vs baseline: 1.3921x; 1.3921x over previous
#include <cuda_runtime.h>
#include <math.h>
#include <stdint.h>

#define ROWS 128
#define NT   512
#define KQ   512
#define KC   768
#define HID  128
#define DIMO 512
#define SCALE 0.17677669529663687f
#define SQRTD 22.627416997969522f

#define SQ 132
#define SA 36
#define SB 136
#define ABUF (ROWS * SA)
#define BBUF (32 * SB)

#define OFF_Q  0
#define OFF_A  (ROWS * SQ)
#define OFF_B  (OFF_A + 2 * ABUF)
#define OFF_S  (OFF_B + 2 * BBUF)
#define OFF_SS (OFF_S + ROWS * 4)
#define SMEMF  (OFF_SS + ROWS)

__device__ __forceinline__ float tf(float x) {
    uint32_t r; asm("cvt.rna.tf32.f32 %0, %1;" : "=r"(r) : "f"(x));
    return __uint_as_float(r);
}

__device__ __forceinline__ void mma8(float* c, uint32_t a0, uint32_t a1, uint32_t a2,
                                     uint32_t a3, uint32_t b0, uint32_t b1) {
    asm volatile(
        "mma.sync.aligned.m16n8k8.row.col.f32.tf32.tf32.f32 "
        "{%0,%1,%2,%3},{%4,%5,%6,%7},{%8,%9},{%0,%1,%2,%3};"
        : "+f"(c[0]), "+f"(c[1]), "+f"(c[2]), "+f"(c[3])
        : "r"(a0), "r"(a1), "r"(a2), "r"(a3), "r"(b0), "r"(b1));
}

// Double-buffered projection GEMM: [128 x 128] = src[128 x K] @ W[K x 128], tf32.
// 16 warps: wr=warp>>2 owns rows 32*wr, wc=warp&3 owns cols 32*wc. acc[2*4][4].
template <int KTOT>
__device__ __forceinline__ void gemm(float (*acc)[4], const float* __restrict__ src, int ld,
                                     const float* __restrict__ W, float* sA, float* sB,
                                     int rowBase, int tid, int wr, int wc, int g, int t) {
#pragma unroll
    for (int i = 0; i < 8; i++) { acc[i][0] = 0.f; acc[i][1] = 0.f; acc[i][2] = 0.f; acc[i][3] = 0.f; }
    float2 pa[4]; float4 pb[2];
#pragma unroll
    for (int i = 0; i < 4; i++) {
        int idx = tid + i * NT; int r = idx >> 4, c2 = (idx & 15) << 1;
        pa[i] = *(const float2*)(src + (size_t)(rowBase + r) * ld + c2);
    }
#pragma unroll
    for (int i = 0; i < 2; i++) {
        int idx = tid + i * NT; int r = idx >> 5, c4 = (idx & 31) << 2;
        pb[i] = *(const float4*)(W + (size_t)r * HID + c4);
    }
#pragma unroll
    for (int i = 0; i < 4; i++) {
        int idx = tid + i * NT; int r = idx >> 4, c2 = (idx & 15) << 1;
        sA[r * SA + c2] = tf(pa[i].x); sA[r * SA + c2 + 1] = tf(pa[i].y);
    }
#pragma unroll
    for (int i = 0; i < 2; i++) {
        int idx = tid + i * NT; int r = idx >> 5, c4 = (idx & 31) << 2;
        float* d = sB + r * SB + c4;
        d[0] = tf(pb[i].x); d[1] = tf(pb[i].y); d[2] = tf(pb[i].z); d[3] = tf(pb[i].w);
    }
    int cur = 0;
#pragma unroll 1
    for (int kc = 0; kc < KTOT; kc += 32) {
        __syncthreads();
        bool more = (kc + 32) < KTOT;
        if (more) {
#pragma unroll
            for (int i = 0; i < 4; i++) {
                int idx = tid + i * NT; int r = idx >> 4, c2 = (idx & 15) << 1;
                pa[i] = *(const float2*)(src + (size_t)(rowBase + r) * ld + kc + 32 + c2);
            }
#pragma unroll
            for (int i = 0; i < 2; i++) {
                int idx = tid + i * NT; int r = idx >> 5, c4 = (idx & 31) << 2;
                pb[i] = *(const float4*)(W + (size_t)(kc + 32 + r) * HID + c4);
            }
        }
        const float* cA = sA + cur * ABUF;
        const float* cB = sB + cur * BBUF;
#pragma unroll
        for (int s8 = 0; s8 < 4; s8++) {
            int k0 = s8 * 8 + t;
            uint32_t a[2][4];
#pragma unroll
            for (int mt = 0; mt < 2; mt++) {
                int r0 = wr * 32 + mt * 16 + g;
                a[mt][0] = __float_as_uint(cA[r0 * SA + k0]);
                a[mt][1] = __float_as_uint(cA[(r0 + 8) * SA + k0]);
                a[mt][2] = __float_as_uint(cA[r0 * SA + k0 + 4]);
                a[mt][3] = __float_as_uint(cA[(r0 + 8) * SA + k0 + 4]);
            }
#pragma unroll
            for (int nt = 0; nt < 4; nt++) {
                int col = wc * 32 + nt * 8 + g;
                uint32_t b0 = __float_as_uint(cB[k0 * SB + col]);
                uint32_t b1 = __float_as_uint(cB[(k0 + 4) * SB + col]);
                mma8(acc[nt],     a[0][0], a[0][1], a[0][2], a[0][3], b0, b1);
                mma8(acc[4 + nt], a[1][0], a[1][1], a[1][2], a[1][3], b0, b1);
            }
        }
        if (more) {
            float* dA = sA + (cur ^ 1) * ABUF;
            float* dB = sB + (cur ^ 1) * BBUF;
#pragma unroll
            for (int i = 0; i < 4; i++) {
                int idx = tid + i * NT; int r = idx >> 4, c2 = (idx & 15) << 1;
                dA[r * SA + c2] = tf(pa[i].x); dA[r * SA + c2 + 1] = tf(pa[i].y);
            }
#pragma unroll
            for (int i = 0; i < 2; i++) {
                int idx = tid + i * NT; int r = idx >> 5, c4 = (idx & 31) << 2;
                float* d = dB + r * SB + c4;
                d[0] = tf(pb[i].x); d[1] = tf(pb[i].y); d[2] = tf(pb[i].z); d[3] = tf(pb[i].w);
            }
        }
        cur ^= 1;
    }
}

__global__ void __launch_bounds__(NT, 1) lca_kernel(
    const float* __restrict__ x, const float* __restrict__ ctx,
    const float* __restrict__ Wq, const float* __restrict__ Wk,
    const float* __restrict__ Wv, const float* __restrict__ Wo,
    const float* __restrict__ bo, const float* __restrict__ gg,
    float* __restrict__ out) {
    extern __shared__ float sm[];
    float* sQ  = sm + OFF_Q;   // 128 x 132: q -> out tile (tf32 bits for phase 4)
    float* sA  = sm + OFF_A;   // double-buffered A chunks
    float* sB  = sm + OFF_B;   // double-buffered B chunks
    float* sS  = sm + OFF_S;   // s[row][head]
    float* sSS = sm + OFF_SS;  // row sum-of-squares

    int tid = threadIdx.x;
    int warp = tid >> 5, lane = tid & 31;
    int wr = warp >> 2, wc = warp & 3, g = lane >> 2, t = lane & 3;
    int rowBase = blockIdx.x * ROWS;
    if (tid < ROWS) sSS[tid] = 0.f;

    float acc[8][4];

    // ---- Phase 1: q = x @ Wq -> sQ ----
    gemm<KQ>(acc, x, KQ, Wq, sA, sB, rowBase, tid, wr, wc, g, t);
#pragma unroll
    for (int mt = 0; mt < 2; mt++)
#pragma unroll
        for (int nt = 0; nt < 4; nt++) {
            int r = wr * 32 + mt * 16 + g, c = wc * 32 + nt * 8 + 2 * t;
            sQ[r * SQ + c]           = acc[mt * 4 + nt][0];
            sQ[r * SQ + c + 1]       = acc[mt * 4 + nt][1];
            sQ[(r + 8) * SQ + c]     = acc[mt * 4 + nt][2];
            sQ[(r + 8) * SQ + c + 1] = acc[mt * 4 + nt][3];
        }
    __syncthreads();

    // softmax per (row, head) * scale, in place: 512 tasks, one per thread
    {
        int r = tid >> 2, h = tid & 3;
        float* p = sQ + r * SQ + h * 32;
        float m = -1e30f;
        for (int j = 0; j < 32; j++) m = fmaxf(m, p[j]);
        float s = 0.f;
        for (int j = 0; j < 32; j++) s += __expf(p[j] - m);
        float inv = SCALE / s;
        for (int j = 0; j < 32; j++) p[j] = __expf(p[j] - m) * inv;
    }
    __syncthreads();

    // ---- Phase 2: k = sigmoid(ctx @ Wk); s[row][head] = sum_d k*q ----
    // each wc owns exactly one head (32 cols)
    gemm<KC>(acc, ctx, KC, Wk, sA, sB, rowBase, tid, wr, wc, g, t);
    {
        float part[2][2] = {};
#pragma unroll
        for (int mt = 0; mt < 2; mt++)
#pragma unroll
            for (int nt = 0; nt < 4; nt++) {
                int r = wr * 32 + mt * 16 + g, c = wc * 32 + nt * 8 + 2 * t;
#pragma unroll
                for (int i = 0; i < 4; i++) {
                    int rr = r + (i >> 1) * 8, cc = c + (i & 1);
                    float kv = 1.f / (1.f + __expf(-acc[mt * 4 + nt][i]));
                    part[mt][i >> 1] += kv * sQ[rr * SQ + cc];
                }
            }
#pragma unroll
        for (int mt = 0; mt < 2; mt++)
#pragma unroll
            for (int rh = 0; rh < 2; rh++) {
                float v = part[mt][rh];
                v += __shfl_xor_sync(0xffffffffu, v, 1);
                v += __shfl_xor_sync(0xffffffffu, v, 2);
                if (t == 0) sS[(wr * 32 + mt * 16 + rh * 8 + g) * 4 + wc] = v;
            }
    }

    // ---- Phase 3: v = ctx @ Wv; out = s*v -> sQ (tf32 bits) ----
    gemm<KC>(acc, ctx, KC, Wv, sA, sB, rowBase, tid, wr, wc, g, t);
#pragma unroll
    for (int mt = 0; mt < 2; mt++)
#pragma unroll
        for (int nt = 0; nt < 4; nt++) {
            int r = wr * 32 + mt * 16 + g, c = wc * 32 + nt * 8 + 2 * t;
#pragma unroll
            for (int i = 0; i < 4; i++) {
                int rr = r + (i >> 1) * 8, cc = c + (i & 1);
                sQ[rr * SQ + cc] = tf(sS[rr * 4 + wc] * acc[mt * 4 + nt][i]);
            }
        }
    __syncthreads();

    // ---- Phase 4: y = out @ Wo + bo; accumulate row sum-squares ----
#pragma unroll 1
    for (int nc = 0; nc < 4; nc++) {
#pragma unroll
        for (int i = 0; i < 8; i++) { acc[i][0] = 0.f; acc[i][1] = 0.f; acc[i][2] = 0.f; acc[i][3] = 0.f; }
        float4 pb[2];
#pragma unroll
        for (int i = 0; i < 2; i++) {
            int idx = tid + i * NT; int r = idx >> 5, c4 = (idx & 31) << 2;
            pb[i] = *(const float4*)(Wo + (size_t)r * DIMO + nc * 128 + c4);
        }
#pragma unroll
        for (int i = 0; i < 2; i++) {
            int idx = tid + i * NT; int r = idx >> 5, c4 = (idx & 31) << 2;
            float* d = sB + r * SB + c4;
            d[0] = tf(pb[i].x); d[1] = tf(pb[i].y); d[2] = tf(pb[i].z); d[3] = tf(pb[i].w);
        }
        int cur = 0;
#pragma unroll 1
        for (int kc = 0; kc < 128; kc += 32) {
            __syncthreads();
            bool more = (kc + 32) < 128;
            if (more) {
#pragma unroll
                for (int i = 0; i < 2; i++) {
                    int idx = tid + i * NT; int r = idx >> 5, c4 = (idx & 31) << 2;
                    pb[i] = *(const float4*)(Wo + (size_t)(kc + 32 + r) * DIMO + nc * 128 + c4);
                }
            }
            const float* cB = sB + cur * BBUF;
#pragma unroll
            for (int s8 = 0; s8 < 4; s8++) {
                int k0 = kc + s8 * 8 + t;
                int kk = s8 * 8 + t;
                uint32_t a[2][4];
#pragma unroll
                for (int mt = 0; mt < 2; mt++) {
                    int r0 = wr * 32 + mt * 16 + g;
                    a[mt][0] = __float_as_uint(sQ[r0 * SQ + k0]);
                    a[mt][1] = __float_as_uint(sQ[(r0 + 8) * SQ + k0]);
                    a[mt][2] = __float_as_uint(sQ[r0 * SQ + k0 + 4]);
                    a[mt][3] = __float_as_uint(sQ[(r0 + 8) * SQ + k0 + 4]);
                }
#pragma unroll
                for (int nt = 0; nt < 4; nt++) {
                    int col = wc * 32 + nt * 8 + g;
                    uint32_t b0 = __float_as_uint(cB[kk * SB + col]);
                    uint32_t b1 = __float_as_uint(cB[(kk + 4) * SB + col]);
                    mma8(acc[nt],     a[0][0], a[0][1], a[0][2], a[0][3], b0, b1);
                    mma8(acc[4 + nt], a[1][0], a[1][1], a[1][2], a[1][3], b0, b1);
                }
            }
            if (more) {
                float* dB = sB + (cur ^ 1) * BBUF;
#pragma unroll
                for (int i = 0; i < 2; i++) {
                    int idx = tid + i * NT; int r = idx >> 5, c4 = (idx & 31) << 2;
                    float* d = dB + r * SB + c4;
                    d[0] = tf(pb[i].x); d[1] = tf(pb[i].y); d[2] = tf(pb[i].z); d[3] = tf(pb[i].w);
                }
            }
            cur ^= 1;
        }
        float rss[2][2] = {};
#pragma unroll
        for (int mt = 0; mt < 2; mt++)
#pragma unroll
            for (int nt = 0; nt < 4; nt++) {
                int r = wr * 32 + mt * 16 + g, c = nc * 128 + wc * 32 + nt * 8 + 2 * t;
#pragma unroll
                for (int i = 0; i < 4; i++) {
                    int rr = r + (i >> 1) * 8, cc = c + (i & 1);
                    float y = acc[mt * 4 + nt][i] + __ldg(bo + cc);
                    out[(size_t)(rowBase + rr) * DIMO + cc] = y;
                    rss[mt][i >> 1] += y * y;
                }
            }
#pragma unroll
        for (int mt = 0; mt < 2; mt++)
#pragma unroll
            for (int rh = 0; rh < 2; rh++) {
                float v = rss[mt][rh];
                v += __shfl_xor_sync(0xffffffffu, v, 1);
                v += __shfl_xor_sync(0xffffffffu, v, 2);
                if (t == 0) atomicAdd(&sSS[wr * 32 + mt * 16 + rh * 8 + g], v);
            }
    }
    __syncthreads();

    // ---- Phase 5: RMS-normalize in place (rows are L2-hot) ----
    for (int i4 = tid; i4 < ROWS * DIMO / 4; i4 += NT) {
        int r = i4 >> 7, c4 = (i4 & 127) << 2;
        float* p = out + (size_t)(rowBase + r) * DIMO + c4;
        float4 y = *(float4*)p;
        float sc = rsqrtf(fmaxf(sSS[r], 1e-24f)) * SQRTD;
        float4 gv = *(const float4*)(gg + c4);
        y.x *= sc * gv.x; y.y *= sc * gv.y; y.z *= sc * gv.z; y.w *= sc * gv.w;
        *(float4*)p = y;
    }
}

extern "C" void kernel_launch(void* const* d_in, const int* in_sizes, int n_in,
                              void* d_out, int out_size) {
    const float* x   = (const float*)d_in[0];
    const float* ctx = (const float*)d_in[1];
    const float* Wq  = (const float*)d_in[2];
    const float* Wk  = (const float*)d_in[3];
    const float* Wv  = (const float*)d_in[4];
    const float* Wo  = (const float*)d_in[5];
    const float* bo  = (const float*)d_in[6];
    const float* gg  = (const float*)d_in[7];
    cudaFuncSetAttribute(lca_kernel, cudaFuncAttributeMaxDynamicSharedMemorySize, SMEMF * 4);
    lca_kernel<<<512, NT, SMEMF * 4>>>(x, ctx, Wq, Wk, Wv, Wo, bo, gg, (float*)d_out);
}

// round 8
// speedup vs baseline: 1.4717x; 1.0571x over previous
#include <cuda_runtime.h>
#include <math.h>
#include <stdint.h>

#define ROWS 128
#define NT   256
#define KQ   512
#define KC   768
#define HID  128
#define DIMO 512
#define SCALE 0.17677669529663687f
#define SQRTD 22.627416997969522f

#define SQ 132
#define SA 36
#define SB 136
#define ABUF (ROWS * SA)   // 4608
#define BBUF (32 * SB)     // 4352

#define OFF_Q  0
#define OFF_A  (ROWS * SQ)            // 16896
#define OFF_B1 (OFF_A + 2 * ABUF)     // 26112
#define OFF_B2 (OFF_B1 + 2 * BBUF)    // 34816
#define OFF_SS (OFF_B2 + 2 * BBUF)    // 43520
#define SMEMF  (OFF_SS + ROWS)        // 43648

__device__ __forceinline__ float tf(float x) {
    uint32_t r; asm("cvt.rna.tf32.f32 %0, %1;" : "=r"(r) : "f"(x));
    return __uint_as_float(r);
}
__device__ __forceinline__ void mma8(float* c, uint32_t a0, uint32_t a1, uint32_t a2,
                                     uint32_t a3, uint32_t b0, uint32_t b1) {
    asm volatile(
        "mma.sync.aligned.m16n8k8.row.col.f32.tf32.tf32.f32 "
        "{%0,%1,%2,%3},{%4,%5,%6,%7},{%8,%9},{%0,%1,%2,%3};"
        : "+f"(c[0]), "+f"(c[1]), "+f"(c[2]), "+f"(c[3])
        : "r"(a0), "r"(a1), "r"(a2), "r"(a3), "r"(b0), "r"(b1));
}
__device__ __forceinline__ float4 tf4(float4 v) {
    v.x = tf(v.x); v.y = tf(v.y); v.z = tf(v.z); v.w = tf(v.w); return v;
}

// Double-buffered GEMM: [128 x 128(x2)] = src[128 x K] @ W1(,W2)[K x 128], tf32.
// 8 warps: wr=warp>>1 rows 32*wr.., wc=warp&1 cols 64*wc. acc[2mt*8nt][4].
template <int KTOT, bool DUAL>
__device__ __forceinline__ void gemm(float (*acc)[4], float (*acc2)[4],
    const float* __restrict__ src, int ld,
    const float* __restrict__ W1, const float* __restrict__ W2,
    float* sA, float* sB1, float* sB2,
    int rowBase, int tid, int wr, int wc, int g, int t) {
#pragma unroll
    for (int i = 0; i < 16; i++) {
        acc[i][0] = acc[i][1] = acc[i][2] = acc[i][3] = 0.f;
        if (DUAL) { acc2[i][0] = acc2[i][1] = acc2[i][2] = acc2[i][3] = 0.f; }
    }
    int ra[4], ca[4], rb[4], cb[4];
#pragma unroll
    for (int j = 0; j < 4; j++) {
        int idx = tid + j * NT;
        ra[j] = idx >> 3; ca[j] = (idx & 7) << 2;
        rb[j] = idx >> 5; cb[j] = (idx & 31) << 2;
    }
    float4 pa[4], pb1[4], pb2[4];
#pragma unroll
    for (int j = 0; j < 4; j++) {
        pa[j]  = *(const float4*)(src + (size_t)(rowBase + ra[j]) * ld + ca[j]);
        pb1[j] = *(const float4*)(W1 + (size_t)rb[j] * HID + cb[j]);
        if (DUAL) pb2[j] = *(const float4*)(W2 + (size_t)rb[j] * HID + cb[j]);
    }
#pragma unroll
    for (int j = 0; j < 4; j++) {
        *(float4*)(sA + ra[j] * SA + ca[j])   = tf4(pa[j]);
        *(float4*)(sB1 + rb[j] * SB + cb[j])  = tf4(pb1[j]);
        if (DUAL) *(float4*)(sB2 + rb[j] * SB + cb[j]) = tf4(pb2[j]);
    }
    int cur = 0;
#pragma unroll 1
    for (int kc = 0; kc < KTOT; kc += 32) {
        __syncthreads();
        bool more = (kc + 32) < KTOT;
        if (more) {
#pragma unroll
            for (int j = 0; j < 4; j++) {
                pa[j]  = *(const float4*)(src + (size_t)(rowBase + ra[j]) * ld + kc + 32 + ca[j]);
                pb1[j] = *(const float4*)(W1 + (size_t)(kc + 32 + rb[j]) * HID + cb[j]);
                if (DUAL) pb2[j] = *(const float4*)(W2 + (size_t)(kc + 32 + rb[j]) * HID + cb[j]);
            }
        }
        const float* cA  = sA  + cur * ABUF;
        const float* cB1 = sB1 + cur * BBUF;
        const float* cB2 = sB2 + cur * BBUF;
#pragma unroll
        for (int s8 = 0; s8 < 4; s8++) {
            int k0 = s8 * 8 + t;
            uint32_t a[2][4];
#pragma unroll
            for (int mt = 0; mt < 2; mt++) {
                int r0 = wr * 32 + mt * 16 + g;
                a[mt][0] = __float_as_uint(cA[r0 * SA + k0]);
                a[mt][1] = __float_as_uint(cA[(r0 + 8) * SA + k0]);
                a[mt][2] = __float_as_uint(cA[r0 * SA + k0 + 4]);
                a[mt][3] = __float_as_uint(cA[(r0 + 8) * SA + k0 + 4]);
            }
#pragma unroll
            for (int nt = 0; nt < 8; nt++) {
                int col = wc * 64 + nt * 8 + g;
                uint32_t b0 = __float_as_uint(cB1[k0 * SB + col]);
                uint32_t b1 = __float_as_uint(cB1[(k0 + 4) * SB + col]);
                mma8(acc[nt],     a[0][0], a[0][1], a[0][2], a[0][3], b0, b1);
                mma8(acc[8 + nt], a[1][0], a[1][1], a[1][2], a[1][3], b0, b1);
                if (DUAL) {
                    uint32_t c0 = __float_as_uint(cB2[k0 * SB + col]);
                    uint32_t c1 = __float_as_uint(cB2[(k0 + 4) * SB + col]);
                    mma8(acc2[nt],     a[0][0], a[0][1], a[0][2], a[0][3], c0, c1);
                    mma8(acc2[8 + nt], a[1][0], a[1][1], a[1][2], a[1][3], c0, c1);
                }
            }
        }
        if (more) {
            float* dA  = sA  + (cur ^ 1) * ABUF;
            float* dB1 = sB1 + (cur ^ 1) * BBUF;
            float* dB2 = sB2 + (cur ^ 1) * BBUF;
#pragma unroll
            for (int j = 0; j < 4; j++) {
                *(float4*)(dA + ra[j] * SA + ca[j])  = tf4(pa[j]);
                *(float4*)(dB1 + rb[j] * SB + cb[j]) = tf4(pb1[j]);
                if (DUAL) *(float4*)(dB2 + rb[j] * SB + cb[j]) = tf4(pb2[j]);
            }
        }
        cur ^= 1;
    }
}

__global__ void __launch_bounds__(NT, 1) lca_kernel(
    const float* __restrict__ x, const float* __restrict__ ctx,
    const float* __restrict__ Wq, const float* __restrict__ Wk,
    const float* __restrict__ Wv, const float* __restrict__ Wo,
    const float* __restrict__ bo, const float* __restrict__ gg,
    float* __restrict__ out) {
    extern __shared__ float sm[];
    float* sQ  = sm + OFF_Q;
    float* sA  = sm + OFF_A;
    float* sB1 = sm + OFF_B1;
    float* sB2 = sm + OFF_B2;
    float* sSS = sm + OFF_SS;

    int tid = threadIdx.x;
    int warp = tid >> 5, lane = tid & 31;
    int wr = warp >> 1, wc = warp & 1, g = lane >> 2, t = lane & 3;
    int rowBase = blockIdx.x * ROWS;
    if (tid < ROWS) sSS[tid] = 0.f;

    float acc[16][4], acc2[16][4];

    // ---- Phase 1: q = x @ Wq -> sQ ----
    gemm<KQ, false>(acc, acc2, x, KQ, Wq, Wq, sA, sB1, sB2, rowBase, tid, wr, wc, g, t);
#pragma unroll
    for (int mt = 0; mt < 2; mt++)
#pragma unroll
        for (int nt = 0; nt < 8; nt++) {
            int r = wr * 32 + mt * 16 + g, c = wc * 64 + nt * 8 + 2 * t;
            sQ[r * SQ + c]           = acc[mt * 8 + nt][0];
            sQ[r * SQ + c + 1]       = acc[mt * 8 + nt][1];
            sQ[(r + 8) * SQ + c]     = acc[mt * 8 + nt][2];
            sQ[(r + 8) * SQ + c + 1] = acc[mt * 8 + nt][3];
        }
    __syncthreads();

    // softmax per (row, head) * scale, in place: 512 tasks / 256 threads
#pragma unroll
    for (int it = 0; it < 2; it++) {
        int task = tid + it * NT;
        int r = task >> 2, h = task & 3;
        float* p = sQ + r * SQ + h * 32;
        float m = -1e30f;
#pragma unroll
        for (int j = 0; j < 32; j++) m = fmaxf(m, p[j]);
        float s = 0.f;
#pragma unroll
        for (int j = 0; j < 32; j++) s += __expf(p[j] - m);
        float inv = SCALE / s;
#pragma unroll
        for (int j = 0; j < 32; j++) p[j] = __expf(p[j] - m) * inv;
    }
    __syncthreads();

    // ---- Phase 2+3 merged: k = sigmoid(ctx@Wk), v = ctx@Wv (one ctx pass) ----
    gemm<KC, true>(acc, acc2, ctx, KC, Wk, Wv, sA, sB1, sB2, rowBase, tid, wr, wc, g, t);
    {
        float part[2][2][2] = {};  // [mt][rowhalf][head-in-wc]
#pragma unroll
        for (int mt = 0; mt < 2; mt++)
#pragma unroll
            for (int nt = 0; nt < 8; nt++) {
                int hl = nt >> 2;
                int r = wr * 32 + mt * 16 + g, c = wc * 64 + nt * 8 + 2 * t;
#pragma unroll
                for (int i = 0; i < 4; i++) {
                    int rr = r + (i >> 1) * 8, cc = c + (i & 1);
                    float kv = 1.f / (1.f + __expf(-acc[mt * 8 + nt][i]));
                    part[mt][i >> 1][hl] += kv * sQ[rr * SQ + cc];
                }
            }
        // butterfly over quad: every lane gets the full head-dot
#pragma unroll
        for (int mt = 0; mt < 2; mt++)
#pragma unroll
            for (int rh = 0; rh < 2; rh++)
#pragma unroll
                for (int hl = 0; hl < 2; hl++) {
                    float v = part[mt][rh][hl];
                    v += __shfl_xor_sync(0xffffffffu, v, 1);
                    v += __shfl_xor_sync(0xffffffffu, v, 2);
                    part[mt][rh][hl] = v;
                }
        // out = s * v -> sQ (tf32 bits), same positions this thread read
#pragma unroll
        for (int mt = 0; mt < 2; mt++)
#pragma unroll
            for (int nt = 0; nt < 8; nt++) {
                int hl = nt >> 2;
                int r = wr * 32 + mt * 16 + g, c = wc * 64 + nt * 8 + 2 * t;
#pragma unroll
                for (int i = 0; i < 4; i++) {
                    int rr = r + (i >> 1) * 8, cc = c + (i & 1);
                    sQ[rr * SQ + cc] = tf(part[mt][i >> 1][hl] * acc2[mt * 8 + nt][i]);
                }
            }
    }
    __syncthreads();

    // ---- Phase 4: y = out @ Wo + bo; row sum-squares; DB over 16 iterations ----
    int rb[4], cb[4];
#pragma unroll
    for (int j = 0; j < 4; j++) {
        int idx = tid + j * NT;
        rb[j] = idx >> 5; cb[j] = (idx & 31) << 2;
    }
    float4 pb[4];
#pragma unroll
    for (int j = 0; j < 4; j++)
        pb[j] = *(const float4*)(Wo + (size_t)rb[j] * DIMO + cb[j]);
#pragma unroll
    for (int j = 0; j < 4; j++)
        *(float4*)(sB1 + rb[j] * SB + cb[j]) = tf4(pb[j]);
    int cur = 0;
#pragma unroll 1
    for (int i = 0; i < 16; i++) {
        int nc = i >> 2, kc = (i & 3) * 32;
        if ((i & 3) == 0) {
#pragma unroll
            for (int q = 0; q < 16; q++) {
                acc[q][0] = acc[q][1] = acc[q][2] = acc[q][3] = 0.f;
            }
        }
        __syncthreads();
        if (i < 15) {
            int n = i + 1, nn = n >> 2, nk = (n & 3) * 32;
#pragma unroll
            for (int j = 0; j < 4; j++)
                pb[j] = *(const float4*)(Wo + (size_t)(nk + rb[j]) * DIMO + nn * 128 + cb[j]);
        }
        const float* cB = sB1 + cur * BBUF;
#pragma unroll
        for (int s8 = 0; s8 < 4; s8++) {
            int k0 = kc + s8 * 8 + t;
            int kk = s8 * 8 + t;
            uint32_t a[2][4];
#pragma unroll
            for (int mt = 0; mt < 2; mt++) {
                int r0 = wr * 32 + mt * 16 + g;
                a[mt][0] = __float_as_uint(sQ[r0 * SQ + k0]);
                a[mt][1] = __float_as_uint(sQ[(r0 + 8) * SQ + k0]);
                a[mt][2] = __float_as_uint(sQ[r0 * SQ + k0 + 4]);
                a[mt][3] = __float_as_uint(sQ[(r0 + 8) * SQ + k0 + 4]);
            }
#pragma unroll
            for (int nt = 0; nt < 8; nt++) {
                int col = wc * 64 + nt * 8 + g;
                uint32_t b0 = __float_as_uint(cB[kk * SB + col]);
                uint32_t b1 = __float_as_uint(cB[(kk + 4) * SB + col]);
                mma8(acc[nt],     a[0][0], a[0][1], a[0][2], a[0][3], b0, b1);
                mma8(acc[8 + nt], a[1][0], a[1][1], a[1][2], a[1][3], b0, b1);
            }
        }
        if (i < 15) {
            float* dB = sB1 + (cur ^ 1) * BBUF;
#pragma unroll
            for (int j = 0; j < 4; j++)
                *(float4*)(dB + rb[j] * SB + cb[j]) = tf4(pb[j]);
        }
        cur ^= 1;
        if ((i & 3) == 3) {  // end of this nc: write y, accumulate sum-squares
            float rss[2][2] = {};
#pragma unroll
            for (int mt = 0; mt < 2; mt++)
#pragma unroll
                for (int nt = 0; nt < 8; nt++) {
                    int r = wr * 32 + mt * 16 + g, c = nc * 128 + wc * 64 + nt * 8 + 2 * t;
#pragma unroll
                    for (int e = 0; e < 4; e++) {
                        int rr = r + (e >> 1) * 8, cc = c + (e & 1);
                        float y = acc[mt * 8 + nt][e] + __ldg(bo + cc);
                        out[(size_t)(rowBase + rr) * DIMO + cc] = y;
                        rss[mt][e >> 1] += y * y;
                    }
                }
#pragma unroll
            for (int mt = 0; mt < 2; mt++)
#pragma unroll
                for (int rh = 0; rh < 2; rh++) {
                    float v = rss[mt][rh];
                    v += __shfl_xor_sync(0xffffffffu, v, 1);
                    v += __shfl_xor_sync(0xffffffffu, v, 2);
                    if (t == 0) atomicAdd(&sSS[wr * 32 + mt * 16 + rh * 8 + g], v);
                }
        }
    }
    __syncthreads();

    // ---- Phase 5: RMS-normalize in place (rows are L2-hot) ----
#pragma unroll 1
    for (int i4 = tid; i4 < ROWS * DIMO / 4; i4 += NT) {
        int r = i4 >> 7, c4 = (i4 & 127) << 2;
        float* p = out + (size_t)(rowBase + r) * DIMO + c4;
        float4 y = *(float4*)p;
        float sc = rsqrtf(fmaxf(sSS[r], 1e-24f)) * SQRTD;
        float4 gv = *(const float4*)(gg + c4);
        y.x *= sc * gv.x; y.y *= sc * gv.y; y.z *= sc * gv.z; y.w *= sc * gv.w;
        *(float4*)p = y;
    }
}

extern "C" void kernel_launch(void* const* d_in, const int* in_sizes, int n_in,
                              void* d_out, int out_size) {
    const float* x   = (const float*)d_in[0];
    const float* ctx = (const float*)d_in[1];
    const float* Wq  = (const float*)d_in[2];
    const float* Wk  = (const float*)d_in[3];
    const float* Wv  = (const float*)d_in[4];
    const float* Wo  = (const float*)d_in[5];
    const float* bo  = (const float*)d_in[6];
    const float* gg  = (const float*)d_in[7];
    cudaFuncSetAttribute(lca_kernel, cudaFuncAttributeMaxDynamicSharedMemorySize, SMEMF * 4);
    lca_kernel<<<512, NT, SMEMF * 4>>>(x, ctx, Wq, Wk, Wv, Wo, bo, gg, (float*)d_out);
}

// round 9
// speedup vs baseline: 1.5178x; 1.0314x over previous
#include <cuda_runtime.h>
#include <math.h>
#include <stdint.h>

#define ROWS 128
#define NT   512
#define KQ   512
#define KC   768
#define HID  128
#define DIMO 512
#define SCALE 0.17677669529663687f
#define SQRTD 22.627416997969522f

#define SQ 132
#define SA 36
#define SB 136
#define ABUF (ROWS * SA)
#define BBUF (32 * SB)

#define OFF_Q  0
#define OFF_A  (ROWS * SQ)            // 16896
#define OFF_B1 (OFF_A + 2 * ABUF)     // 26112
#define OFF_B2 (OFF_B1 + 2 * BBUF)    // 34816
#define OFF_S  (OFF_B2 + 2 * BBUF)    // 43520
#define OFF_SS (OFF_S + ROWS * 4)     // 44032
#define SMEMF  (OFF_SS + ROWS)        // 44160 floats = 176640 B

__device__ __forceinline__ float tf(float x) {
    uint32_t r; asm("cvt.rna.tf32.f32 %0, %1;" : "=r"(r) : "f"(x));
    return __uint_as_float(r);
}
__device__ __forceinline__ void mma8(float* c, uint32_t a0, uint32_t a1, uint32_t a2,
                                     uint32_t a3, uint32_t b0, uint32_t b1) {
    asm volatile(
        "mma.sync.aligned.m16n8k8.row.col.f32.tf32.tf32.f32 "
        "{%0,%1,%2,%3},{%4,%5,%6,%7},{%8,%9},{%0,%1,%2,%3};"
        : "+f"(c[0]), "+f"(c[1]), "+f"(c[2]), "+f"(c[3])
        : "r"(a0), "r"(a1), "r"(a2), "r"(a3), "r"(b0), "r"(b1));
}
__device__ __forceinline__ float4 tf4(float4 v) {
    v.x = tf(v.x); v.y = tf(v.y); v.z = tf(v.z); v.w = tf(v.w); return v;
}

__global__ void __launch_bounds__(NT, 1) lca_kernel(
    const float* __restrict__ x, const float* __restrict__ ctx,
    const float* __restrict__ Wq, const float* __restrict__ Wk,
    const float* __restrict__ Wv, const float* __restrict__ Wo,
    const float* __restrict__ bo, const float* __restrict__ gg,
    float* __restrict__ out) {
    extern __shared__ float sm[];
    float* sQ  = sm + OFF_Q;
    float* sA  = sm + OFF_A;
    float* sB1 = sm + OFF_B1;
    float* sB2 = sm + OFF_B2;
    float* sS  = sm + OFF_S;
    float* sSS = sm + OFF_SS;

    int tid = threadIdx.x;
    int warp = tid >> 5, lane = tid & 31;
    int g = lane >> 2, t = lane & 3;
    // 16-warp 32x32 ids (phase 1)
    int wr4 = warp >> 2, wc4 = warp & 3;
    // 8-warp-group 32x64 ids (phases 2+3, 4)
    int grp = warp >> 3, w8 = warp & 7, wr = w8 >> 1, wcg = w8 & 1;
    int rowBase = blockIdx.x * ROWS;
    if (tid < ROWS) sSS[tid] = 0.f;

    // fill index precompute (512 threads)
    int ra[2], ca[2], rb[2], cb[2];
#pragma unroll
    for (int j = 0; j < 2; j++) {
        int idx = tid + j * NT;
        ra[j] = idx >> 3; ca[j] = (idx & 7) << 2;
        rb[j] = idx >> 5; cb[j] = (idx & 31) << 2;
    }

    float acc[16][4];

    // ================= Phase 1: q = x @ Wq (16 warps, 32x32 tiles) =================
    {
#pragma unroll
        for (int i = 0; i < 8; i++) { acc[i][0] = acc[i][1] = acc[i][2] = acc[i][3] = 0.f; }
        float4 pa[2], pb[2];
#pragma unroll
        for (int j = 0; j < 2; j++) {
            pa[j] = *(const float4*)(x + (size_t)(rowBase + ra[j]) * KQ + ca[j]);
            pb[j] = *(const float4*)(Wq + (size_t)rb[j] * HID + cb[j]);
        }
#pragma unroll
        for (int j = 0; j < 2; j++) {
            *(float4*)(sA + ra[j] * SA + ca[j])  = tf4(pa[j]);
            *(float4*)(sB1 + rb[j] * SB + cb[j]) = tf4(pb[j]);
        }
        int cur = 0;
#pragma unroll 1
        for (int kc = 0; kc < KQ; kc += 32) {
            __syncthreads();
            bool more = (kc + 32) < KQ;
            if (more) {
#pragma unroll
                for (int j = 0; j < 2; j++) {
                    pa[j] = *(const float4*)(x + (size_t)(rowBase + ra[j]) * KQ + kc + 32 + ca[j]);
                    pb[j] = *(const float4*)(Wq + (size_t)(kc + 32 + rb[j]) * HID + cb[j]);
                }
            }
            const float* cA = sA + cur * ABUF;
            const float* cB = sB1 + cur * BBUF;
#pragma unroll
            for (int s8 = 0; s8 < 4; s8++) {
                int k0 = s8 * 8 + t;
                uint32_t a[2][4];
#pragma unroll
                for (int mt = 0; mt < 2; mt++) {
                    int r0 = wr4 * 32 + mt * 16 + g;
                    a[mt][0] = __float_as_uint(cA[r0 * SA + k0]);
                    a[mt][1] = __float_as_uint(cA[(r0 + 8) * SA + k0]);
                    a[mt][2] = __float_as_uint(cA[r0 * SA + k0 + 4]);
                    a[mt][3] = __float_as_uint(cA[(r0 + 8) * SA + k0 + 4]);
                }
#pragma unroll
                for (int nt = 0; nt < 4; nt++) {
                    int col = wc4 * 32 + nt * 8 + g;
                    uint32_t b0 = __float_as_uint(cB[k0 * SB + col]);
                    uint32_t b1 = __float_as_uint(cB[(k0 + 4) * SB + col]);
                    mma8(acc[nt],     a[0][0], a[0][1], a[0][2], a[0][3], b0, b1);
                    mma8(acc[4 + nt], a[1][0], a[1][1], a[1][2], a[1][3], b0, b1);
                }
            }
            if (more) {
                float* dA = sA + (cur ^ 1) * ABUF;
                float* dB = sB1 + (cur ^ 1) * BBUF;
#pragma unroll
                for (int j = 0; j < 2; j++) {
                    *(float4*)(dA + ra[j] * SA + ca[j])  = tf4(pa[j]);
                    *(float4*)(dB + rb[j] * SB + cb[j]) = tf4(pb[j]);
                }
            }
            cur ^= 1;
        }
#pragma unroll
        for (int mt = 0; mt < 2; mt++)
#pragma unroll
            for (int nt = 0; nt < 4; nt++) {
                int r = wr4 * 32 + mt * 16 + g, c = wc4 * 32 + nt * 8 + 2 * t;
                sQ[r * SQ + c]           = acc[mt * 4 + nt][0];
                sQ[r * SQ + c + 1]       = acc[mt * 4 + nt][1];
                sQ[(r + 8) * SQ + c]     = acc[mt * 4 + nt][2];
                sQ[(r + 8) * SQ + c + 1] = acc[mt * 4 + nt][3];
            }
        __syncthreads();
    }

    // softmax per (row, head) * scale, in place: one task per thread
    {
        int r = tid >> 2, h = tid & 3;
        float* p = sQ + r * SQ + h * 32;
        float m = -1e30f;
#pragma unroll
        for (int j = 0; j < 32; j++) m = fmaxf(m, p[j]);
        float s = 0.f;
#pragma unroll
        for (int j = 0; j < 32; j++) s += __expf(p[j] - m);
        float inv = SCALE / s;
#pragma unroll
        for (int j = 0; j < 32; j++) p[j] = __expf(p[j] - m) * inv;
    }
    __syncthreads();

    // ======= Phase 2+3: group0 k=ctx@Wk, group1 v=ctx@Wv (shared A, one pass) =======
    {
#pragma unroll
        for (int i = 0; i < 16; i++) { acc[i][0] = acc[i][1] = acc[i][2] = acc[i][3] = 0.f; }
        float4 pa[2], pb1[2], pb2[2];
#pragma unroll
        for (int j = 0; j < 2; j++) {
            pa[j]  = *(const float4*)(ctx + (size_t)(rowBase + ra[j]) * KC + ca[j]);
            pb1[j] = *(const float4*)(Wk + (size_t)rb[j] * HID + cb[j]);
            pb2[j] = *(const float4*)(Wv + (size_t)rb[j] * HID + cb[j]);
        }
#pragma unroll
        for (int j = 0; j < 2; j++) {
            *(float4*)(sA + ra[j] * SA + ca[j])   = tf4(pa[j]);
            *(float4*)(sB1 + rb[j] * SB + cb[j])  = tf4(pb1[j]);
            *(float4*)(sB2 + rb[j] * SB + cb[j])  = tf4(pb2[j]);
        }
        const float* myB = grp ? sB2 : sB1;
        int cur = 0;
#pragma unroll 1
        for (int kc = 0; kc < KC; kc += 32) {
            __syncthreads();
            bool more = (kc + 32) < KC;
            if (more) {
#pragma unroll
                for (int j = 0; j < 2; j++) {
                    pa[j]  = *(const float4*)(ctx + (size_t)(rowBase + ra[j]) * KC + kc + 32 + ca[j]);
                    pb1[j] = *(const float4*)(Wk + (size_t)(kc + 32 + rb[j]) * HID + cb[j]);
                    pb2[j] = *(const float4*)(Wv + (size_t)(kc + 32 + rb[j]) * HID + cb[j]);
                }
            }
            const float* cA = sA + cur * ABUF;
            const float* cB = myB + cur * BBUF;
#pragma unroll
            for (int s8 = 0; s8 < 4; s8++) {
                int k0 = s8 * 8 + t;
                uint32_t a[2][4];
#pragma unroll
                for (int mt = 0; mt < 2; mt++) {
                    int r0 = wr * 32 + mt * 16 + g;
                    a[mt][0] = __float_as_uint(cA[r0 * SA + k0]);
                    a[mt][1] = __float_as_uint(cA[(r0 + 8) * SA + k0]);
                    a[mt][2] = __float_as_uint(cA[r0 * SA + k0 + 4]);
                    a[mt][3] = __float_as_uint(cA[(r0 + 8) * SA + k0 + 4]);
                }
#pragma unroll
                for (int nt = 0; nt < 8; nt++) {
                    int col = wcg * 64 + nt * 8 + g;
                    uint32_t b0 = __float_as_uint(cB[k0 * SB + col]);
                    uint32_t b1 = __float_as_uint(cB[(k0 + 4) * SB + col]);
                    mma8(acc[nt],     a[0][0], a[0][1], a[0][2], a[0][3], b0, b1);
                    mma8(acc[8 + nt], a[1][0], a[1][1], a[1][2], a[1][3], b0, b1);
                }
            }
            if (more) {
                float* dA  = sA  + (cur ^ 1) * ABUF;
                float* dB1 = sB1 + (cur ^ 1) * BBUF;
                float* dB2 = sB2 + (cur ^ 1) * BBUF;
#pragma unroll
                for (int j = 0; j < 2; j++) {
                    *(float4*)(dA + ra[j] * SA + ca[j])   = tf4(pa[j]);
                    *(float4*)(dB1 + rb[j] * SB + cb[j])  = tf4(pb1[j]);
                    *(float4*)(dB2 + rb[j] * SB + cb[j])  = tf4(pb2[j]);
                }
            }
            cur ^= 1;
        }
        // k-group: s[row][head] = <sigmoid(k), q>  (each warp covers 2 full heads)
        if (grp == 0) {
            float part[2][2][2] = {};
#pragma unroll
            for (int mt = 0; mt < 2; mt++)
#pragma unroll
                for (int nt = 0; nt < 8; nt++) {
                    int hl = nt >> 2;
                    int r = wr * 32 + mt * 16 + g, c = wcg * 64 + nt * 8 + 2 * t;
#pragma unroll
                    for (int e = 0; e < 4; e++) {
                        int rr = r + (e >> 1) * 8, cc = c + (e & 1);
                        float kv = 1.f / (1.f + __expf(-acc[mt * 8 + nt][e]));
                        part[mt][e >> 1][hl] += kv * sQ[rr * SQ + cc];
                    }
                }
#pragma unroll
            for (int mt = 0; mt < 2; mt++)
#pragma unroll
                for (int rh = 0; rh < 2; rh++)
#pragma unroll
                    for (int hl = 0; hl < 2; hl++) {
                        float v = part[mt][rh][hl];
                        v += __shfl_xor_sync(0xffffffffu, v, 1);
                        v += __shfl_xor_sync(0xffffffffu, v, 2);
                        if (t == 0)
                            sS[(wr * 32 + mt * 16 + rh * 8 + g) * 4 + wcg * 2 + hl] = v;
                    }
        }
        __syncthreads();
        // v-group: out = s*v -> sQ (tf32 bits)
        if (grp == 1) {
#pragma unroll
            for (int mt = 0; mt < 2; mt++)
#pragma unroll
                for (int nt = 0; nt < 8; nt++) {
                    int hl = nt >> 2;
                    int r = wr * 32 + mt * 16 + g, c = wcg * 64 + nt * 8 + 2 * t;
#pragma unroll
                    for (int e = 0; e < 4; e++) {
                        int rr = r + (e >> 1) * 8, cc = c + (e & 1);
                        float s = sS[rr * 4 + wcg * 2 + hl];
                        sQ[rr * SQ + cc] = tf(s * acc[mt * 8 + nt][e]);
                    }
                }
        }
        __syncthreads();
    }

    // ===== Phase 4: y = out @ Wo + bo; two nc blocks concurrently (one per group) =====
    {
        int gt = tid & 255;
        int rb4[4], cb4[4];
#pragma unroll
        for (int j = 0; j < 4; j++) {
            int idx = gt + j * 256;
            rb4[j] = idx >> 5; cb4[j] = (idx & 31) << 2;
        }
        float* sBg = grp ? sB2 : sB1;
        float4 pb[4];
#pragma unroll
        for (int j = 0; j < 4; j++)
            pb[j] = *(const float4*)(Wo + (size_t)rb4[j] * DIMO + grp * 128 + cb4[j]);
#pragma unroll
        for (int j = 0; j < 4; j++)
            *(float4*)(sBg + rb4[j] * SB + cb4[j]) = tf4(pb[j]);
        int cur = 0;
#pragma unroll 1
        for (int i = 0; i < 8; i++) {
            int pair = i >> 2, kc = (i & 3) * 32;
            int nc = pair * 2 + grp;
            if ((i & 3) == 0) {
#pragma unroll
                for (int q = 0; q < 16; q++) { acc[q][0] = acc[q][1] = acc[q][2] = acc[q][3] = 0.f; }
            }
            __syncthreads();
            if (i < 7) {
                int n = i + 1, nk = (n & 3) * 32, nnc = (n >> 2) * 2 + grp;
#pragma unroll
                for (int j = 0; j < 4; j++)
                    pb[j] = *(const float4*)(Wo + (size_t)(nk + rb4[j]) * DIMO + nnc * 128 + cb4[j]);
            }
            const float* cB = sBg + cur * BBUF;
#pragma unroll
            for (int s8 = 0; s8 < 4; s8++) {
                int k0 = kc + s8 * 8 + t;
                int kk = s8 * 8 + t;
                uint32_t a[2][4];
#pragma unroll
                for (int mt = 0; mt < 2; mt++) {
                    int r0 = wr * 32 + mt * 16 + g;
                    a[mt][0] = __float_as_uint(sQ[r0 * SQ + k0]);
                    a[mt][1] = __float_as_uint(sQ[(r0 + 8) * SQ + k0]);
                    a[mt][2] = __float_as_uint(sQ[r0 * SQ + k0 + 4]);
                    a[mt][3] = __float_as_uint(sQ[(r0 + 8) * SQ + k0 + 4]);
                }
#pragma unroll
                for (int nt = 0; nt < 8; nt++) {
                    int col = wcg * 64 + nt * 8 + g;
                    uint32_t b0 = __float_as_uint(cB[kk * SB + col]);
                    uint32_t b1 = __float_as_uint(cB[(kk + 4) * SB + col]);
                    mma8(acc[nt],     a[0][0], a[0][1], a[0][2], a[0][3], b0, b1);
                    mma8(acc[8 + nt], a[1][0], a[1][1], a[1][2], a[1][3], b0, b1);
                }
            }
            if (i < 7) {
                float* dB = sBg + (cur ^ 1) * BBUF;
#pragma unroll
                for (int j = 0; j < 4; j++)
                    *(float4*)(dB + rb4[j] * SB + cb4[j]) = tf4(pb[j]);
            }
            cur ^= 1;
            if ((i & 3) == 3) {  // finish nc block: write y, accumulate sum-squares
                float rss[2][2] = {};
#pragma unroll
                for (int mt = 0; mt < 2; mt++)
#pragma unroll
                    for (int nt = 0; nt < 8; nt++) {
                        int r = wr * 32 + mt * 16 + g;
                        int c = nc * 128 + wcg * 64 + nt * 8 + 2 * t;
#pragma unroll
                        for (int e = 0; e < 4; e++) {
                            int rr = r + (e >> 1) * 8, cc = c + (e & 1);
                            float y = acc[mt * 8 + nt][e] + __ldg(bo + cc);
                            out[(size_t)(rowBase + rr) * DIMO + cc] = y;
                            rss[mt][e >> 1] += y * y;
                        }
                    }
#pragma unroll
                for (int mt = 0; mt < 2; mt++)
#pragma unroll
                    for (int rh = 0; rh < 2; rh++) {
                        float v = rss[mt][rh];
                        v += __shfl_xor_sync(0xffffffffu, v, 1);
                        v += __shfl_xor_sync(0xffffffffu, v, 2);
                        if (t == 0) atomicAdd(&sSS[wr * 32 + mt * 16 + rh * 8 + g], v);
                    }
            }
        }
    }
    __syncthreads();

    // ---- Phase 5: RMS-normalize in place (rows are L2-hot) ----
#pragma unroll 1
    for (int i4 = tid; i4 < ROWS * DIMO / 4; i4 += NT) {
        int r = i4 >> 7, c4 = (i4 & 127) << 2;
        float* p = out + (size_t)(rowBase + r) * DIMO + c4;
        float4 y = *(float4*)p;
        float sc = rsqrtf(fmaxf(sSS[r], 1e-24f)) * SQRTD;
        float4 gv = *(const float4*)(gg + c4);
        y.x *= sc * gv.x; y.y *= sc * gv.y; y.z *= sc * gv.z; y.w *= sc * gv.w;
        *(float4*)p = y;
    }
}

extern "C" void kernel_launch(void* const* d_in, const int* in_sizes, int n_in,
                              void* d_out, int out_size) {
    const float* x   = (const float*)d_in[0];
    const float* ctx = (const float*)d_in[1];
    const float* Wq  = (const float*)d_in[2];
    const float* Wk  = (const float*)d_in[3];
    const float* Wv  = (const float*)d_in[4];
    const float* Wo  = (const float*)d_in[5];
    const float* bo  = (const float*)d_in[6];
    const float* gg  = (const float*)d_in[7];
    cudaFuncSetAttribute(lca_kernel, cudaFuncAttributeMaxDynamicSharedMemorySize, SMEMF * 4);
    lca_kernel<<<512, NT, SMEMF * 4>>>(x, ctx, Wq, Wk, Wv, Wo, bo, gg, (float*)d_out);
}

// round 10
// speedup vs baseline: 1.6780x; 1.1056x over previous
#include <cuda_runtime.h>
#include <math.h>
#include <stdint.h>

#define ROWS 128
#define NT   512
#define KQ   512
#define KC   768
#define HID  128
#define DIMO 512
#define SCALE 0.17677669529663687f
#define SQRTD 22.627416997969522f

#define SQ 132
#define SA 36
#define SB 36
#define ABUF (ROWS * SA)
#define BBUF (128 * SB)
#define ABUF4 (ABUF * 4)
#define BBUF4 (BBUF * 4)

#define OFF_Q  0
#define OFF_A  (ROWS * SQ)             // 16896
#define OFF_B1 (OFF_A + 2 * ABUF)      // 26112
#define OFF_B2 (OFF_B1 + 2 * BBUF)     // 35328
#define OFF_S  (OFF_B2 + 2 * BBUF)     // 44544
#define OFF_SS (OFF_S + ROWS * 4)      // 45056
#define SMEMF  (OFF_SS + ROWS)         // 45184 floats = 180736 B

// pre-transposed tf32 weights, n-major:
// WqT[128][512] | WkT[128][768] | WvT[128][768] | WoT[512][128]
__device__ float g_wt[327680];

__device__ __forceinline__ float tf(float x) {
    uint32_t r; asm("cvt.rna.tf32.f32 %0, %1;" : "=r"(r) : "f"(x));
    return __uint_as_float(r);
}
__device__ __forceinline__ float4 tf4(float4 v) {
    v.x = tf(v.x); v.y = tf(v.y); v.z = tf(v.z); v.w = tf(v.w); return v;
}
__device__ __forceinline__ void mma8(float* c, uint32_t a0, uint32_t a1, uint32_t a2,
                                     uint32_t a3, uint32_t b0, uint32_t b1) {
    asm volatile(
        "mma.sync.aligned.m16n8k8.row.col.f32.tf32.tf32.f32 "
        "{%0,%1,%2,%3},{%4,%5,%6,%7},{%8,%9},{%0,%1,%2,%3};"
        : "+f"(c[0]), "+f"(c[1]), "+f"(c[2]), "+f"(c[3])
        : "r"(a0), "r"(a1), "r"(a2), "r"(a3), "r"(b0), "r"(b1));
}
__device__ __forceinline__ void ldsm4(uint32_t* r, uint32_t a) {
    asm volatile("ldmatrix.sync.aligned.m8n8.x4.shared.b16 {%0,%1,%2,%3}, [%4];"
                 : "=r"(r[0]), "=r"(r[1]), "=r"(r[2]), "=r"(r[3]) : "r"(a));
}
__device__ __forceinline__ uint32_t s2u(const void* p) {
    return (uint32_t)__cvta_generic_to_shared(p);
}

// ---------- weight transpose + tf32 pre-pass ----------
__global__ void wtrans(const float* __restrict__ Wq, const float* __restrict__ Wk,
                       const float* __restrict__ Wv, const float* __restrict__ Wo) {
    __shared__ float t[32][33];
    int bid = blockIdx.x;
    const float* src; float* dst; int K, N, toff;
    if (bid < 64)       { src = Wq; dst = g_wt;          K = 512; N = 128; toff = bid; }
    else if (bid < 160) { src = Wk; dst = g_wt + 65536;  K = 768; N = 128; toff = bid - 64; }
    else if (bid < 256) { src = Wv; dst = g_wt + 163840; K = 768; N = 128; toff = bid - 160; }
    else                { src = Wo; dst = g_wt + 262144; K = 128; N = 512; toff = bid - 256; }
    int ntx = N / 32;
    int tn = (toff % ntx) * 32, tk = (toff / ntx) * 32;
    for (int i = threadIdx.y; i < 32; i += 8)
        t[i][threadIdx.x] = src[(size_t)(tk + i) * N + tn + threadIdx.x];
    __syncthreads();
    for (int i = threadIdx.y; i < 32; i += 8)
        dst[(size_t)(tn + i) * K + tk + threadIdx.x] = tf(t[threadIdx.x][i]);
}

__global__ void __launch_bounds__(NT, 1) lca_kernel(
    const float* __restrict__ x, const float* __restrict__ ctx,
    const float* __restrict__ bo, const float* __restrict__ gg,
    float* __restrict__ out) {
    extern __shared__ float sm[];
    float* sQ  = sm + OFF_Q;
    float* sA  = sm + OFF_A;
    float* sB1 = sm + OFF_B1;
    float* sB2 = sm + OFF_B2;
    float* sS  = sm + OFF_S;
    float* sSS = sm + OFF_SS;
    uint32_t sQu = s2u(sQ), sAu = s2u(sA), sB1u = s2u(sB1), sB2u = s2u(sB2);

    int tid = threadIdx.x;
    int warp = tid >> 5, lane = tid & 31;
    int g = lane >> 2, t = lane & 3;
    int wr4 = warp >> 2, wc4 = warp & 3;                    // 16-warp ids (phase 1)
    int grp = warp >> 3, w8 = warp & 7, wr = w8 >> 1, wcg = w8 & 1;  // 8-warp-group ids
    int rowBase = blockIdx.x * ROWS;
    if (tid < ROWS) sSS[tid] = 0.f;

    // ldmatrix lane offsets (bytes)
    uint32_t aOff = (uint32_t)(((lane & 15) * SA + ((lane >> 4) << 2)) * 4);
    uint32_t bOff = (uint32_t)((((((lane >> 4) << 3) + (lane & 7)) * SB) + (((lane >> 3) & 1) << 2)) * 4);
    uint32_t qOff = (uint32_t)(((lane & 15) * SQ + ((lane >> 4) << 2)) * 4);

    // fill indices: 1024 float4s per tile, 2 iters of 512 threads
    int rr8[2], kk4[2];
#pragma unroll
    for (int j = 0; j < 2; j++) {
        int idx = tid + j * NT;
        rr8[j] = idx >> 3; kk4[j] = (idx & 7) << 2;
    }

    float acc[16][4];
    const float* WqT = g_wt;
    const float* WkT = g_wt + 65536;
    const float* WvT = g_wt + 163840;
    const float* WoT = g_wt + 262144;

    // ================= Phase 1: q = x @ Wq (16 warps, 32x32 tiles) =================
    {
#pragma unroll
        for (int i = 0; i < 8; i++) { acc[i][0] = acc[i][1] = acc[i][2] = acc[i][3] = 0.f; }
        float4 pa[2], pb[2];
#pragma unroll
        for (int j = 0; j < 2; j++) {
            pa[j] = *(const float4*)(x + (size_t)(rowBase + rr8[j]) * KQ + kk4[j]);
            pb[j] = *(const float4*)(WqT + (size_t)rr8[j] * KQ + kk4[j]);
        }
#pragma unroll
        for (int j = 0; j < 2; j++) {
            *(float4*)(sA + rr8[j] * SA + kk4[j])  = tf4(pa[j]);
            *(float4*)(sB1 + rr8[j] * SB + kk4[j]) = pb[j];
        }
        uint32_t aB = (uint32_t)(wr4 * 32 * SA * 4) + aOff;
        uint32_t bB = (uint32_t)(wc4 * 32 * SB * 4) + bOff;
        int cur = 0;
#pragma unroll 1
        for (int kc = 0; kc < KQ; kc += 32) {
            __syncthreads();
            bool more = (kc + 32) < KQ;
            if (more) {
#pragma unroll
                for (int j = 0; j < 2; j++) {
                    pa[j] = *(const float4*)(x + (size_t)(rowBase + rr8[j]) * KQ + kc + 32 + kk4[j]);
                    pb[j] = *(const float4*)(WqT + (size_t)rr8[j] * KQ + kc + 32 + kk4[j]);
                }
            }
            uint32_t cA = sAu + cur * ABUF4 + aB;
            uint32_t cB = sB1u + cur * BBUF4 + bB;
#pragma unroll
            for (int s8 = 0; s8 < 4; s8++) {
                uint32_t a0[4], a1[4];
                ldsm4(a0, cA + s8 * 32);
                ldsm4(a1, cA + 16 * SA * 4 + s8 * 32);
#pragma unroll
                for (int p = 0; p < 2; p++) {
                    uint32_t b[4];
                    ldsm4(b, cB + p * (16 * SB * 4) + s8 * 32);
                    mma8(acc[2 * p],     a0[0], a0[1], a0[2], a0[3], b[0], b[1]);
                    mma8(acc[2 * p + 1], a0[0], a0[1], a0[2], a0[3], b[2], b[3]);
                    mma8(acc[4 + 2 * p],     a1[0], a1[1], a1[2], a1[3], b[0], b[1]);
                    mma8(acc[4 + 2 * p + 1], a1[0], a1[1], a1[2], a1[3], b[2], b[3]);
                }
            }
            if (more) {
                float* dA = sA + (cur ^ 1) * ABUF;
                float* dB = sB1 + (cur ^ 1) * BBUF;
#pragma unroll
                for (int j = 0; j < 2; j++) {
                    *(float4*)(dA + rr8[j] * SA + kk4[j]) = tf4(pa[j]);
                    *(float4*)(dB + rr8[j] * SB + kk4[j]) = pb[j];
                }
            }
            cur ^= 1;
        }
#pragma unroll
        for (int mt = 0; mt < 2; mt++)
#pragma unroll
            for (int nt = 0; nt < 4; nt++) {
                int r = wr4 * 32 + mt * 16 + g, c = wc4 * 32 + nt * 8 + 2 * t;
                sQ[r * SQ + c]           = acc[mt * 4 + nt][0];
                sQ[r * SQ + c + 1]       = acc[mt * 4 + nt][1];
                sQ[(r + 8) * SQ + c]     = acc[mt * 4 + nt][2];
                sQ[(r + 8) * SQ + c + 1] = acc[mt * 4 + nt][3];
            }
        __syncthreads();
    }

    // softmax per (row, head) * scale, in place: one task per thread
    {
        int r = tid >> 2, h = tid & 3;
        float* p = sQ + r * SQ + h * 32;
        float m = -1e30f;
#pragma unroll
        for (int j = 0; j < 32; j++) m = fmaxf(m, p[j]);
        float s = 0.f;
#pragma unroll
        for (int j = 0; j < 32; j++) s += __expf(p[j] - m);
        float inv = SCALE / s;
#pragma unroll
        for (int j = 0; j < 32; j++) p[j] = __expf(p[j] - m) * inv;
    }
    __syncthreads();

    // ======= Phase 2+3: group0 k=ctx@Wk, group1 v=ctx@Wv (shared A, one pass) =======
    {
#pragma unroll
        for (int i = 0; i < 16; i++) { acc[i][0] = acc[i][1] = acc[i][2] = acc[i][3] = 0.f; }
        float4 pa[2], pb1[2], pb2[2];
#pragma unroll
        for (int j = 0; j < 2; j++) {
            pa[j]  = *(const float4*)(ctx + (size_t)(rowBase + rr8[j]) * KC + kk4[j]);
            pb1[j] = *(const float4*)(WkT + (size_t)rr8[j] * KC + kk4[j]);
            pb2[j] = *(const float4*)(WvT + (size_t)rr8[j] * KC + kk4[j]);
        }
#pragma unroll
        for (int j = 0; j < 2; j++) {
            *(float4*)(sA + rr8[j] * SA + kk4[j])  = tf4(pa[j]);
            *(float4*)(sB1 + rr8[j] * SB + kk4[j]) = pb1[j];
            *(float4*)(sB2 + rr8[j] * SB + kk4[j]) = pb2[j];
        }
        uint32_t aB = (uint32_t)(wr * 32 * SA * 4) + aOff;
        uint32_t bB = (uint32_t)(wcg * 64 * SB * 4) + bOff;
        uint32_t myBu = grp ? sB2u : sB1u;
        int cur = 0;
#pragma unroll 1
        for (int kc = 0; kc < KC; kc += 32) {
            __syncthreads();
            bool more = (kc + 32) < KC;
            if (more) {
#pragma unroll
                for (int j = 0; j < 2; j++) {
                    pa[j]  = *(const float4*)(ctx + (size_t)(rowBase + rr8[j]) * KC + kc + 32 + kk4[j]);
                    pb1[j] = *(const float4*)(WkT + (size_t)rr8[j] * KC + kc + 32 + kk4[j]);
                    pb2[j] = *(const float4*)(WvT + (size_t)rr8[j] * KC + kc + 32 + kk4[j]);
                }
            }
            uint32_t cA = sAu + cur * ABUF4 + aB;
            uint32_t cB = myBu + cur * BBUF4 + bB;
#pragma unroll
            for (int s8 = 0; s8 < 4; s8++) {
                uint32_t a0[4], a1[4];
                ldsm4(a0, cA + s8 * 32);
                ldsm4(a1, cA + 16 * SA * 4 + s8 * 32);
#pragma unroll
                for (int p = 0; p < 4; p++) {
                    uint32_t b[4];
                    ldsm4(b, cB + p * (16 * SB * 4) + s8 * 32);
                    mma8(acc[2 * p],     a0[0], a0[1], a0[2], a0[3], b[0], b[1]);
                    mma8(acc[2 * p + 1], a0[0], a0[1], a0[2], a0[3], b[2], b[3]);
                    mma8(acc[8 + 2 * p],     a1[0], a1[1], a1[2], a1[3], b[0], b[1]);
                    mma8(acc[8 + 2 * p + 1], a1[0], a1[1], a1[2], a1[3], b[2], b[3]);
                }
            }
            if (more) {
                float* dA  = sA  + (cur ^ 1) * ABUF;
                float* dB1 = sB1 + (cur ^ 1) * BBUF;
                float* dB2 = sB2 + (cur ^ 1) * BBUF;
#pragma unroll
                for (int j = 0; j < 2; j++) {
                    *(float4*)(dA + rr8[j] * SA + kk4[j])  = tf4(pa[j]);
                    *(float4*)(dB1 + rr8[j] * SB + kk4[j]) = pb1[j];
                    *(float4*)(dB2 + rr8[j] * SB + kk4[j]) = pb2[j];
                }
            }
            cur ^= 1;
        }
        // k-group: s[row][head] = <sigmoid(k), q>
        if (grp == 0) {
            float part[2][2][2] = {};
#pragma unroll
            for (int mt = 0; mt < 2; mt++)
#pragma unroll
                for (int nt = 0; nt < 8; nt++) {
                    int hl = nt >> 2;
                    int r = wr * 32 + mt * 16 + g, c = wcg * 64 + nt * 8 + 2 * t;
#pragma unroll
                    for (int e = 0; e < 4; e++) {
                        int rr = r + (e >> 1) * 8, cc = c + (e & 1);
                        float kv = 1.f / (1.f + __expf(-acc[mt * 8 + nt][e]));
                        part[mt][e >> 1][hl] += kv * sQ[rr * SQ + cc];
                    }
                }
#pragma unroll
            for (int mt = 0; mt < 2; mt++)
#pragma unroll
                for (int rh = 0; rh < 2; rh++)
#pragma unroll
                    for (int hl = 0; hl < 2; hl++) {
                        float v = part[mt][rh][hl];
                        v += __shfl_xor_sync(0xffffffffu, v, 1);
                        v += __shfl_xor_sync(0xffffffffu, v, 2);
                        if (t == 0)
                            sS[(wr * 32 + mt * 16 + rh * 8 + g) * 4 + wcg * 2 + hl] = v;
                    }
        }
        __syncthreads();
        // v-group: out = s*v -> sQ (tf32 bits)
        if (grp == 1) {
#pragma unroll
            for (int mt = 0; mt < 2; mt++)
#pragma unroll
                for (int nt = 0; nt < 8; nt++) {
                    int hl = nt >> 2;
                    int r = wr * 32 + mt * 16 + g, c = wcg * 64 + nt * 8 + 2 * t;
#pragma unroll
                    for (int e = 0; e < 4; e++) {
                        int rr = r + (e >> 1) * 8, cc = c + (e & 1);
                        float s = sS[rr * 4 + wcg * 2 + hl];
                        sQ[rr * SQ + cc] = tf(s * acc[mt * 8 + nt][e]);
                    }
                }
        }
        __syncthreads();
    }

    // ===== Phase 4: y = out @ Wo + bo; two nc blocks concurrently (one per group) =====
    {
        int gt = tid & 255;
        int rn[4], rk[4];
#pragma unroll
        for (int j = 0; j < 4; j++) {
            int idx = gt + j * 256;
            rn[j] = idx >> 3; rk[j] = (idx & 7) << 2;
        }
        float* sBg = grp ? sB2 : sB1;
        uint32_t sBgu = grp ? sB2u : sB1u;
        float4 pb[4];
#pragma unroll
        for (int j = 0; j < 4; j++)
            pb[j] = *(const float4*)(WoT + (size_t)(grp * 128 + rn[j]) * HID + rk[j]);
#pragma unroll
        for (int j = 0; j < 4; j++)
            *(float4*)(sBg + rn[j] * SB + rk[j]) = pb[j];
        uint32_t bB = (uint32_t)(wcg * 64 * SB * 4) + bOff;
        uint32_t qB = (uint32_t)(wr * 32 * SQ * 4) + qOff;
        int cur = 0;
#pragma unroll 1
        for (int i = 0; i < 8; i++) {
            int pair = i >> 2, kc = (i & 3) * 32;
            int nc = pair * 2 + grp;
            if ((i & 3) == 0) {
#pragma unroll
                for (int q = 0; q < 16; q++) { acc[q][0] = acc[q][1] = acc[q][2] = acc[q][3] = 0.f; }
            }
            __syncthreads();
            if (i < 7) {
                int n = i + 1, nk = (n & 3) * 32, nnc = (n >> 2) * 2 + grp;
#pragma unroll
                for (int j = 0; j < 4; j++)
                    pb[j] = *(const float4*)(WoT + (size_t)(nnc * 128 + rn[j]) * HID + nk + rk[j]);
            }
            uint32_t cB = sBgu + cur * BBUF4 + bB;
            uint32_t cQ = sQu + qB + kc * 4;
#pragma unroll
            for (int s8 = 0; s8 < 4; s8++) {
                uint32_t a0[4], a1[4];
                ldsm4(a0, cQ + s8 * 32);
                ldsm4(a1, cQ + 16 * SQ * 4 + s8 * 32);
#pragma unroll
                for (int p = 0; p < 4; p++) {
                    uint32_t b[4];
                    ldsm4(b, cB + p * (16 * SB * 4) + s8 * 32);
                    mma8(acc[2 * p],     a0[0], a0[1], a0[2], a0[3], b[0], b[1]);
                    mma8(acc[2 * p + 1], a0[0], a0[1], a0[2], a0[3], b[2], b[3]);
                    mma8(acc[8 + 2 * p],     a1[0], a1[1], a1[2], a1[3], b[0], b[1]);
                    mma8(acc[8 + 2 * p + 1], a1[0], a1[1], a1[2], a1[3], b[2], b[3]);
                }
            }
            if (i < 7) {
                float* dB = sBg + (cur ^ 1) * BBUF;
#pragma unroll
                for (int j = 0; j < 4; j++)
                    *(float4*)(dB + rn[j] * SB + rk[j]) = pb[j];
            }
            cur ^= 1;
            if ((i & 3) == 3) {  // finish nc block: write y, accumulate sum-squares
                float rss[2][2] = {};
#pragma unroll
                for (int mt = 0; mt < 2; mt++)
#pragma unroll
                    for (int nt = 0; nt < 8; nt++) {
                        int r = wr * 32 + mt * 16 + g;
                        int c = nc * 128 + wcg * 64 + nt * 8 + 2 * t;
#pragma unroll
                        for (int e = 0; e < 4; e++) {
                            int rr = r + (e >> 1) * 8, cc = c + (e & 1);
                            float y = acc[mt * 8 + nt][e] + __ldg(bo + cc);
                            out[(size_t)(rowBase + rr) * DIMO + cc] = y;
                            rss[mt][e >> 1] += y * y;
                        }
                    }
#pragma unroll
                for (int mt = 0; mt < 2; mt++)
#pragma unroll
                    for (int rh = 0; rh < 2; rh++) {
                        float v = rss[mt][rh];
                        v += __shfl_xor_sync(0xffffffffu, v, 1);
                        v += __shfl_xor_sync(0xffffffffu, v, 2);
                        if (t == 0) atomicAdd(&sSS[wr * 32 + mt * 16 + rh * 8 + g], v);
                    }
            }
        }
    }
    __syncthreads();

    // ---- Phase 5: RMS-normalize in place (rows are L2-hot) ----
#pragma unroll 1
    for (int i4 = tid; i4 < ROWS * DIMO / 4; i4 += NT) {
        int r = i4 >> 7, c4 = (i4 & 127) << 2;
        float* p = out + (size_t)(rowBase + r) * DIMO + c4;
        float4 y = *(float4*)p;
        float sc = rsqrtf(fmaxf(sSS[r], 1e-24f)) * SQRTD;
        float4 gv = *(const float4*)(gg + c4);
        y.x *= sc * gv.x; y.y *= sc * gv.y; y.z *= sc * gv.z; y.w *= sc * gv.w;
        *(float4*)p = y;
    }
}

extern "C" void kernel_launch(void* const* d_in, const int* in_sizes, int n_in,
                              void* d_out, int out_size) {
    const float* x   = (const float*)d_in[0];
    const float* ctx = (const float*)d_in[1];
    const float* Wq  = (const float*)d_in[2];
    const float* Wk  = (const float*)d_in[3];
    const float* Wv  = (const float*)d_in[4];
    const float* Wo  = (const float*)d_in[5];
    const float* bo  = (const float*)d_in[6];
    const float* gg  = (const float*)d_in[7];
    wtrans<<<320, dim3(32, 8)>>>(Wq, Wk, Wv, Wo);
    cudaFuncSetAttribute(lca_kernel, cudaFuncAttributeMaxDynamicSharedMemorySize, SMEMF * 4);
    lca_kernel<<<512, NT, SMEMF * 4>>>(x, ctx, bo, gg, (float*)d_out);
}